// round 5
// baseline (speedup 1.0000x reference)
#include <cuda_runtime.h>

#define NNODES 100000
#define NEDGES 1600000
#define FDIM   128

// Scratch (device globals — no allocation allowed anywhere)
__device__ float g_h[(size_t)NNODES * FDIM];   // GEMM output (messages)
__device__ float g_a[(size_t)NNODES * FDIM];   // aggregated features
__device__ float g_dis[NNODES];                // (deg+1)^{-1/2}
__device__ int   g_deg[NNODES];                // in-degree (edges only)
__device__ int   g_rowp[NNODES + 1];           // CSR row pointers (by dst)
__device__ int   g_cursor[NNODES];             // scatter cursors
__device__ int   g_col[NEDGES];                // src node per CSR slot
__device__ int   g_bsum[512];                  // per-block scan sums
__device__ int   g_boff[512];                  // scanned block offsets
__device__ int   g_is64;                       // edge dtype flag (1 = int64)

// ---------------------------------------------------------------------------
// Edge dtype detection: int64 little-endian with values < 2^31 has every odd
// int32 word == 0. If ANY odd word is nonzero over the whole buffer, it's int32.
// ---------------------------------------------------------------------------
__global__ void k_init_flag() { g_is64 = 1; }

__global__ void k_detect(const int* __restrict__ p, int twoE) {
    int i = blockIdx.x * blockDim.x + threadIdx.x;
    int idx = 2 * i + 1;
    if (idx < twoE && p[idx] != 0) g_is64 = 0;   // plain store, same value
}

__device__ __forceinline__ int load_edge(const void* ei, size_t idx, int is64) {
    if (is64) return (int)((const long long*)ei)[idx];
    return ((const int*)ei)[idx];
}

// ---------------------------------------------------------------------------
// CSR build
// ---------------------------------------------------------------------------
__global__ void k_zero_deg(int n) {
    int i = blockIdx.x * blockDim.x + threadIdx.x;
    if (i < n) g_deg[i] = 0;
}

__global__ void k_zero_col(int E) {
    int i = blockIdx.x * blockDim.x + threadIdx.x;
    if (i < E && i < NEDGES) g_col[i] = 0;
}

__global__ void k_count_deg(const void* __restrict__ ei, int E, int n) {
    int e = blockIdx.x * blockDim.x + threadIdx.x;
    if (e >= E) return;
    int is64 = g_is64;
    int d = load_edge(ei, (size_t)E + e, is64);        // dst row
    if ((unsigned)d < (unsigned)n) atomicAdd(&g_deg[d], 1);
}

// Per-block exclusive scan of g_deg (256 elems/block) + block totals.
__global__ void __launch_bounds__(256) k_scan_block(int n) {
    __shared__ int s[256];
    int tid = threadIdx.x;
    int i = blockIdx.x * 256 + tid;
    int v = (i < n) ? g_deg[i] : 0;
    s[tid] = v;
    __syncthreads();
    for (int off = 1; off < 256; off <<= 1) {
        int t = (tid >= off) ? s[tid - off] : 0;
        __syncthreads();
        s[tid] += t;
        __syncthreads();
    }
    if (i < n) g_rowp[i] = s[tid] - v;                 // exclusive within block
    if (tid == 255 && blockIdx.x < 512) g_bsum[blockIdx.x] = s[255];
}

// Exclusive scan of the block sums (nb <= 512), single block.
__global__ void __launch_bounds__(512) k_scan_spine(int nb) {
    __shared__ int s[512];
    int tid = threadIdx.x;
    int v = (tid < nb) ? g_bsum[tid] : 0;
    s[tid] = v;
    __syncthreads();
    for (int off = 1; off < 512; off <<= 1) {
        int t = (tid >= off) ? s[tid - off] : 0;
        __syncthreads();
        s[tid] += t;
        __syncthreads();
    }
    g_boff[tid] = s[tid] - v;
}

// Add spine offsets; init cursors; compute dis = rsqrt(deg+1); rowp[n] = E.
__global__ void k_finalize(int n, int E) {
    int i = blockIdx.x * blockDim.x + threadIdx.x;
    if (i >= n) return;
    int r = g_rowp[i] + g_boff[(i >> 8) & 511];
    g_rowp[i] = r;
    g_cursor[i] = r;
    g_dis[i] = rsqrtf((float)(g_deg[i] + 1));
    if (i == 0) g_rowp[n] = E;
}

__global__ void k_scatter(const void* __restrict__ ei, int E, int n) {
    int e = blockIdx.x * blockDim.x + threadIdx.x;
    if (e >= E) return;
    int is64 = g_is64;
    int s = load_edge(ei, (size_t)e, is64);
    int d = load_edge(ei, (size_t)E + e, is64);
    if ((unsigned)s >= (unsigned)n || (unsigned)d >= (unsigned)n) return;
    int pos = atomicAdd(&g_cursor[d], 1);
    if ((unsigned)pos < (unsigned)NEDGES) g_col[pos] = s;
}

// ---------------------------------------------------------------------------
// GEMM: H[M,128] = f(X + bias_in)[M,128] @ W[128,128]
// Block: 128 threads, tile 32 rows x 128 cols; thread computes 8 rows x 4 cols.
// ---------------------------------------------------------------------------
__global__ void __launch_bounds__(128)
k_gemm128(const float* __restrict__ X, const float* __restrict__ W,
          float* __restrict__ H, const float* __restrict__ bias_in,
          int relu_in, int M)
{
    __shared__ float Xs[32 * 128];

    int tid = threadIdx.x;
    int cg  = tid & 31;    // column group: cols cg*4 .. cg*4+3
    int rg  = tid >> 5;    // row group:   rows rg*8 .. rg*8+7

    int t0 = blockIdx.x * 32;
    if (t0 >= M) return;

    #pragma unroll
    for (int i = 0; i < 8; i++) {
        int idx = (tid + i * 128) * 4;
        float4 v = *(const float4*)&X[(size_t)t0 * FDIM + idx];
        if (bias_in) {
            int c = idx & 127;
            v.x += bias_in[c];     v.y += bias_in[c + 1];
            v.z += bias_in[c + 2]; v.w += bias_in[c + 3];
        }
        if (relu_in) {
            v.x = fmaxf(v.x, 0.f); v.y = fmaxf(v.y, 0.f);
            v.z = fmaxf(v.z, 0.f); v.w = fmaxf(v.w, 0.f);
        }
        *(float4*)&Xs[idx] = v;
    }
    __syncthreads();

    float acc[8][4];
    #pragma unroll
    for (int r = 0; r < 8; r++)
        #pragma unroll
        for (int c = 0; c < 4; c++) acc[r][c] = 0.f;

    const float4* Wp = (const float4*)W + cg;

    #pragma unroll 4
    for (int k = 0; k < 128; k += 4) {
        float4 xk[8];
        #pragma unroll
        for (int r = 0; r < 8; r++)
            xk[r] = *(const float4*)&Xs[(rg * 8 + r) * 128 + k];

        float4 w0 = __ldg(Wp + (size_t)(k + 0) * 32);
        float4 w1 = __ldg(Wp + (size_t)(k + 1) * 32);
        float4 w2 = __ldg(Wp + (size_t)(k + 2) * 32);
        float4 w3 = __ldg(Wp + (size_t)(k + 3) * 32);

        #pragma unroll
        for (int r = 0; r < 8; r++) {
            acc[r][0] = fmaf(xk[r].x, w0.x, acc[r][0]);
            acc[r][1] = fmaf(xk[r].x, w0.y, acc[r][1]);
            acc[r][2] = fmaf(xk[r].x, w0.z, acc[r][2]);
            acc[r][3] = fmaf(xk[r].x, w0.w, acc[r][3]);

            acc[r][0] = fmaf(xk[r].y, w1.x, acc[r][0]);
            acc[r][1] = fmaf(xk[r].y, w1.y, acc[r][1]);
            acc[r][2] = fmaf(xk[r].y, w1.z, acc[r][2]);
            acc[r][3] = fmaf(xk[r].y, w1.w, acc[r][3]);

            acc[r][0] = fmaf(xk[r].z, w2.x, acc[r][0]);
            acc[r][1] = fmaf(xk[r].z, w2.y, acc[r][1]);
            acc[r][2] = fmaf(xk[r].z, w2.z, acc[r][2]);
            acc[r][3] = fmaf(xk[r].z, w2.w, acc[r][3]);

            acc[r][0] = fmaf(xk[r].w, w3.x, acc[r][0]);
            acc[r][1] = fmaf(xk[r].w, w3.y, acc[r][1]);
            acc[r][2] = fmaf(xk[r].w, w3.z, acc[r][2]);
            acc[r][3] = fmaf(xk[r].w, w3.w, acc[r][3]);
        }
    }

    #pragma unroll
    for (int r = 0; r < 8; r++) {
        int row = t0 + rg * 8 + r;
        *(float4*)&H[(size_t)row * FDIM + cg * 4] =
            make_float4(acc[r][0], acc[r][1], acc[r][2], acc[r][3]);
    }
}

// ---------------------------------------------------------------------------
// Aggregation (CSR gather): one warp per dst node.
// a[d] = dis[d]^2 * h[d] + sum_{s in in(d)} dis[s]*dis[d] * h[s]
// ---------------------------------------------------------------------------
__global__ void __launch_bounds__(256)
k_agg(const float* __restrict__ H, float* __restrict__ A, int n, int E)
{
    int node = (blockIdx.x * blockDim.x + threadIdx.x) >> 5;
    int lane = threadIdx.x & 31;
    if (node >= n) return;

    float di = g_dis[node];
    int beg = g_rowp[node];
    int end = g_rowp[node + 1];
    if (beg < 0) beg = 0;
    if (end > E) end = E;

    // self-loop
    float4 acc = *(const float4*)&H[(size_t)node * FDIM + lane * 4];
    float s2 = di * di;
    acc.x *= s2; acc.y *= s2; acc.z *= s2; acc.w *= s2;

    for (int e = beg; e < end; e++) {
        int s0 = g_col[e];
        if ((unsigned)s0 >= (unsigned)n) s0 = 0;   // guard (dead if CSR correct)
        float w0 = di * g_dis[s0];
        float4 v0 = *(const float4*)&H[(size_t)s0 * FDIM + lane * 4];
        acc.x = fmaf(v0.x, w0, acc.x); acc.y = fmaf(v0.y, w0, acc.y);
        acc.z = fmaf(v0.z, w0, acc.z); acc.w = fmaf(v0.w, w0, acc.w);
    }

    *(float4*)&A[(size_t)node * FDIM + lane * 4] = acc;
}

// ---------------------------------------------------------------------------
// Final linear: OUT[M,40] = (X + b3)[M,128] @ Wl[128,40] + bl
// ---------------------------------------------------------------------------
__global__ void __launch_bounds__(256)
k_gemm40(const float* __restrict__ X, const float* __restrict__ Wl,
         const float* __restrict__ bl, const float* __restrict__ bias_in,
         float* __restrict__ OUT, int M)
{
    __shared__ float Ws[128 * 40];
    __shared__ float xs[8][128];

    int tid  = threadIdx.x;
    int lane = tid & 31;
    int w    = tid >> 5;

    for (int i = tid; i < 128 * 40; i += 256) Ws[i] = Wl[i];
    __syncthreads();

    int col2 = 32 + (lane & 7);
    int nwarps = gridDim.x * 8;

    for (int r = blockIdx.x * 8 + w; r < M; r += nwarps) {
        float4 v = *(const float4*)&X[(size_t)r * FDIM + lane * 4];
        int c = lane * 4;
        v.x += bias_in[c];     v.y += bias_in[c + 1];
        v.z += bias_in[c + 2]; v.w += bias_in[c + 3];
        *(float4*)&xs[w][lane * 4] = v;
        __syncwarp();

        float acc0 = 0.f, acc1 = 0.f;
        #pragma unroll 8
        for (int k = 0; k < 128; k++) {
            float xv = xs[w][k];
            acc0 = fmaf(xv, Ws[k * 40 + lane], acc0);
            acc1 = fmaf(xv, Ws[k * 40 + col2], acc1);
        }
        OUT[(size_t)r * 40 + lane] = acc0 + bl[lane];
        if (lane < 8)
            OUT[(size_t)r * 40 + 32 + lane] = acc1 + bl[32 + lane];
        __syncwarp();
    }
}

// ---------------------------------------------------------------------------
extern "C" void kernel_launch(void* const* d_in, const int* in_sizes, int n_in,
                              void* d_out, int out_size)
{
    const float* x  = (const float*)d_in[0];
    const void*  ei = d_in[1];
    const float* W1 = (const float*)d_in[2];
    const float* b1 = (const float*)d_in[3];
    const float* W2 = (const float*)d_in[4];
    const float* b2 = (const float*)d_in[5];
    const float* W3 = (const float*)d_in[6];
    const float* b3 = (const float*)d_in[7];
    const float* Wl = (const float*)d_in[8];
    const float* bl = (const float*)d_in[9];
    float* out = (float*)d_out;

    int N = in_sizes[0] / FDIM;   // 100000
    int E = in_sizes[1] / 2;      // 1600000
    if (N > NNODES) N = NNODES;
    if (E > NEDGES) E = NEDGES;

    float *hp = nullptr, *ap = nullptr;
    cudaGetSymbolAddress((void**)&hp, g_h);
    cudaGetSymbolAddress((void**)&ap, g_a);

    int nb = (N + 255) / 256;     // 391 scan blocks
    int eb = (E + 255) / 256;

    // --- edge dtype detection (int64 vs int32) ---
    k_init_flag<<<1, 1>>>();
    k_detect   <<<eb, 256>>>((const int*)ei, 2 * E);

    // --- CSR build + normalization ---
    k_zero_deg  <<<nb, 256>>>(N);
    k_zero_col  <<<eb, 256>>>(E);
    k_count_deg <<<eb, 256>>>(ei, E, N);
    k_scan_block<<<nb, 256>>>(N);
    k_scan_spine<<<1, 512>>>(nb);
    k_finalize  <<<nb, 256>>>(N, E);
    k_scatter   <<<eb, 256>>>(ei, E, N);

    int gemm_blocks = (N + 31) / 32;
    int agg_blocks  = (N * 32 + 255) / 256;   // one warp per node

    // Layer 1: h = x @ W1 ; a = Agg(h)
    k_gemm128<<<gemm_blocks, 128>>>(x, W1, hp, nullptr, 0, N);
    k_agg    <<<agg_blocks, 256>>>(hp, ap, N, E);

    // Layer 2: h = relu(a + b1) @ W2 ; a = Agg(h)
    k_gemm128<<<gemm_blocks, 128>>>(ap, W2, hp, b1, 1, N);
    k_agg    <<<agg_blocks, 256>>>(hp, ap, N, E);

    // Layer 3: h = relu(a + b2) @ W3 ; a = Agg(h)
    k_gemm128<<<gemm_blocks, 128>>>(ap, W3, hp, b2, 1, N);
    k_agg    <<<agg_blocks, 256>>>(hp, ap, N, E);

    // Head: out = (a + b3) @ Wl + bl
    k_gemm40<<<2048, 256>>>(ap, Wl, bl, b3, out, N);
}